// round 1
// baseline (speedup 1.0000x reference)
#include <cuda_runtime.h>
#include <cuda_bf16.h>
#include <cstdint>
#include <math.h>

// Problem dims (fixed by the reference)
static constexpr int B_ROWS = 8192;
static constexpr int F_DIM  = 1024;
static constexpr int N_DIM  = 4096;

// GEMM tiling
static constexpr int BM = 128, BN = 128, BK = 32;
static constexpr int PAD = 8;             // halves of padding per smem row
static constexpr int LDT = BK + PAD;      // 40 halves = 80 bytes per row

// Scratch (device globals: allocation-free per harness rules)
__device__ __align__(16) __nv_bfloat16 g_xb[(size_t)B_ROWS * F_DIM];
__device__ __align__(16) __nv_bfloat16 g_yb[(size_t)B_ROWS * F_DIM];
__device__ __align__(16) __nv_bfloat16 g_wb[(size_t)N_DIM  * F_DIM];
__device__ float g_sumexp[B_ROWS];
__device__ float g_addvec[B_ROWS];

// ---------------------------------------------------------------------------
// fp32 -> bf16 conversion (vectorized, grid-stride). which: 0=x, 1=y, 2=w
// ---------------------------------------------------------------------------
__global__ void k_convert(const float4* __restrict__ in, int n4, int which) {
    __nv_bfloat162* out = (which == 0) ? (__nv_bfloat162*)g_xb
                        : (which == 1) ? (__nv_bfloat162*)g_yb
                                       : (__nv_bfloat162*)g_wb;
    int i  = blockIdx.x * blockDim.x + threadIdx.x;
    int st = gridDim.x * blockDim.x;
    for (; i < n4; i += st) {
        float4 v = in[i];
        out[2*i]   = __floats2bfloat162_rn(v.x, v.y);
        out[2*i+1] = __floats2bfloat162_rn(v.z, v.w);
    }
}

__global__ void k_zero_sumexp() {
    int i = blockIdx.x * blockDim.x + threadIdx.x;
    if (i < B_ROWS) g_sumexp[i] = 0.0f;
}

__global__ void k_finalize() {
    int i = blockIdx.x * blockDim.x + threadIdx.x;
    if (i < B_ROWS) {
        float l = logf(g_sumexp[i]);
        float h = l * fminf(fmaxf(l + 3.0f, 0.0f), 6.0f) * (1.0f / 6.0f);
        g_addvec[i] = h;
    }
}

// ---------------------------------------------------------------------------
// PTX helpers
// ---------------------------------------------------------------------------
__device__ __forceinline__ uint32_t su32(const void* p) {
    return (uint32_t)__cvta_generic_to_shared(p);
}

__device__ __forceinline__ void cp_async16(void* smem, const void* gmem) {
    asm volatile("cp.async.cg.shared.global [%0], [%1], 16;\n"
                 :: "r"(su32(smem)), "l"(gmem));
}

__device__ __forceinline__ void ldsm_x4(uint32_t& r0, uint32_t& r1,
                                        uint32_t& r2, uint32_t& r3, uint32_t addr) {
    asm volatile("ldmatrix.sync.aligned.m8n8.x4.shared.b16 {%0,%1,%2,%3}, [%4];"
                 : "=r"(r0), "=r"(r1), "=r"(r2), "=r"(r3) : "r"(addr));
}

__device__ __forceinline__ void mma_bf16(float* c, const uint32_t* a, const uint32_t* b) {
    asm volatile(
        "mma.sync.aligned.m16n8k16.row.col.f32.bf16.bf16.f32 "
        "{%0,%1,%2,%3}, {%4,%5,%6,%7}, {%8,%9}, {%0,%1,%2,%3};"
        : "+f"(c[0]), "+f"(c[1]), "+f"(c[2]), "+f"(c[3])
        : "r"(a[0]), "r"(a[1]), "r"(a[2]), "r"(a[3]), "r"(b[0]), "r"(b[1]));
}

__device__ __forceinline__ float clamp1(float v) {
    return fminf(fmaxf(v, -1.0f), 1.0f);
}

// ---------------------------------------------------------------------------
// Warp-tiled bf16 GEMM (CTA 128x128, BK=32, 8 warps of 64x32, double-buffered
// cp.async). MODE 0: A=x, B=y, epilogue = sum(exp(score)) per row (atomic).
//            MODE 1: A=y, B=W, epilogue = clamp(acc + bias[n] + addvec[b]).
// ---------------------------------------------------------------------------
template <int MODE>
__global__ void __launch_bounds__(256, 1)
k_gemm(const float* __restrict__ bias, float* __restrict__ out) {
    __shared__ __nv_bfloat16 sA[2][BM * LDT];
    __shared__ __nv_bfloat16 sB[2][BN * LDT];
    __shared__ float s_sum[BM];

    const int tid    = threadIdx.x;
    const int lane   = tid & 31;
    const int warp   = tid >> 5;
    const int warp_m = warp & 1;   // 2 warps along M -> 64 rows each
    const int warp_n = warp >> 1;  // 4 warps along N -> 32 cols each
    const int g      = lane >> 2;  // accum group row
    const int t      = lane & 3;   // accum col pair

    const int i0 = blockIdx.x * BM;
    const int j0 = blockIdx.y * BN;

    const __nv_bfloat16* Ag = ((MODE == 0) ? g_xb : g_yb) + (size_t)i0 * F_DIM;
    const __nv_bfloat16* Bg = ((MODE == 0) ? g_yb : g_wb) + (size_t)j0 * F_DIM;

    if (MODE == 0 && tid < BM) s_sum[tid] = 0.0f;

    float acc[4][4][4];
    #pragma unroll
    for (int mf = 0; mf < 4; mf++)
        #pragma unroll
        for (int nf = 0; nf < 4; nf++)
            #pragma unroll
            for (int k = 0; k < 4; k++) acc[mf][nf][k] = 0.0f;

    // Tile loader: 128 rows x 32 halves (64B) per matrix = 4 x 16B chunks/row.
    // 512 chunks per matrix, 256 threads -> 2 chunks each.
    auto load_tile = [&](int buf, int k0) {
        #pragma unroll
        for (int p = 0; p < 2; p++) {
            int chunk = tid + p * 256;
            int row = chunk >> 2, cc = chunk & 3;
            cp_async16(&sA[buf][row * LDT + cc * 8],
                       Ag + (size_t)row * F_DIM + k0 + cc * 8);
            cp_async16(&sB[buf][row * LDT + cc * 8],
                       Bg + (size_t)row * F_DIM + k0 + cc * 8);
        }
        asm volatile("cp.async.commit_group;\n");
    };

    const int NK = F_DIM / BK;  // 32
    load_tile(0, 0);

    for (int kt = 0; kt < NK; kt++) {
        const int buf = kt & 1;
        if (kt + 1 < NK) {
            load_tile(buf ^ 1, (kt + 1) * BK);
            asm volatile("cp.async.wait_group 1;\n");
        } else {
            asm volatile("cp.async.wait_group 0;\n");
        }
        __syncthreads();

        #pragma unroll
        for (int ks = 0; ks < 2; ks++) {
            uint32_t afr[4][4];
            uint32_t bfr[4][2];
            const int q = lane >> 3, r = lane & 7;

            // A fragments: one ldmatrix.x4 per 16-row m-frag
            #pragma unroll
            for (int mf = 0; mf < 4; mf++) {
                int row = warp_m * 64 + mf * 16 + r + ((q & 1) ? 8 : 0);
                int col = ks * 16 + ((q >= 2) ? 8 : 0);
                ldsm_x4(afr[mf][0], afr[mf][1], afr[mf][2], afr[mf][3],
                        su32(&sA[buf][row * LDT + col]));
            }
            // B fragments: one ldmatrix.x4 covers two adjacent 8-col n-frags
            #pragma unroll
            for (int np = 0; np < 2; np++) {
                int row = warp_n * 32 + np * 16 + r + (q >> 1) * 8;
                int col = ks * 16 + (q & 1) * 8;
                ldsm_x4(bfr[2*np][0], bfr[2*np][1], bfr[2*np+1][0], bfr[2*np+1][1],
                        su32(&sB[buf][row * LDT + col]));
            }
            #pragma unroll
            for (int mf = 0; mf < 4; mf++)
                #pragma unroll
                for (int nf = 0; nf < 4; nf++)
                    mma_bf16(acc[mf][nf], afr[mf], bfr[nf]);
        }
        __syncthreads();
    }

    if (MODE == 0) {
        // epilogue: per-row sum of exp(score) over this 128-col tile
        #pragma unroll
        for (int mf = 0; mf < 4; mf++) {
            float v0 = 0.0f, v1 = 0.0f;
            #pragma unroll
            for (int nf = 0; nf < 4; nf++) {
                v0 += __expf(acc[mf][nf][0]) + __expf(acc[mf][nf][1]);
                v1 += __expf(acc[mf][nf][2]) + __expf(acc[mf][nf][3]);
            }
            // reduce across the 4 lanes (t=0..3) sharing each row
            v0 += __shfl_xor_sync(0xffffffffu, v0, 1);
            v0 += __shfl_xor_sync(0xffffffffu, v0, 2);
            v1 += __shfl_xor_sync(0xffffffffu, v1, 1);
            v1 += __shfl_xor_sync(0xffffffffu, v1, 2);
            if (t == 0) {
                atomicAdd(&s_sum[warp_m * 64 + mf * 16 + g],     v0);
                atomicAdd(&s_sum[warp_m * 64 + mf * 16 + 8 + g], v1);
            }
        }
        __syncthreads();
        if (tid < BM) atomicAdd(&g_sumexp[i0 + tid], s_sum[tid]);
    } else {
        // epilogue: out = clamp(acc + bias[n] + addvec[b]), fp32 float2 stores
        #pragma unroll
        for (int mf = 0; mf < 4; mf++) {
            int r0 = i0 + warp_m * 64 + mf * 16 + g;
            float av0 = g_addvec[r0];
            float av1 = g_addvec[r0 + 8];
            #pragma unroll
            for (int nf = 0; nf < 4; nf++) {
                int c = j0 + warp_n * 32 + nf * 8 + 2 * t;
                float b0 = bias[c], b1 = bias[c + 1];
                float2 o0, o1;
                o0.x = clamp1(acc[mf][nf][0] + b0 + av0);
                o0.y = clamp1(acc[mf][nf][1] + b1 + av0);
                o1.x = clamp1(acc[mf][nf][2] + b0 + av1);
                o1.y = clamp1(acc[mf][nf][3] + b1 + av1);
                *(float2*)&out[(size_t)r0 * N_DIM + c]       = o0;
                *(float2*)&out[(size_t)(r0 + 8) * N_DIM + c] = o1;
            }
        }
    }
}

// ---------------------------------------------------------------------------
// Launch sequence (graph-capturable: kernel launches only, default stream)
// ---------------------------------------------------------------------------
extern "C" void kernel_launch(void* const* d_in, const int* in_sizes, int n_in,
                              void* d_out, int out_size) {
    const float* x    = (const float*)d_in[0];  // [8192,1024]
    const float* y    = (const float*)d_in[1];  // [8192,1024]
    const float* w    = (const float*)d_in[2];  // [4096,1024]
    const float* bias = (const float*)d_in[3];  // [4096]
    float* out = (float*)d_out;                 // [8192,4096]

    const int nxy4 = B_ROWS * F_DIM / 4;
    const int nw4  = N_DIM  * F_DIM / 4;

    k_convert<<<2048, 256>>>((const float4*)x, nxy4, 0);
    k_convert<<<2048, 256>>>((const float4*)y, nxy4, 1);
    k_convert<<<1024, 256>>>((const float4*)w, nw4, 2);
    k_zero_sumexp<<<(B_ROWS + 255) / 256, 256>>>();

    dim3 grid1(B_ROWS / BM, B_ROWS / BN);   // 64 x 64
    k_gemm<0><<<grid1, 256>>>(bias, out);

    k_finalize<<<(B_ROWS + 255) / 256, 256>>>();

    dim3 grid2(B_ROWS / BM, N_DIM / BN);    // 64 x 32
    k_gemm<1><<<grid2, 256>>>(bias, out);
}

// round 4
// speedup vs baseline: 10.5063x; 10.5063x over previous
#include <cuda_runtime.h>
#include <cuda_bf16.h>
#include <cstdint>
#include <math.h>

// Problem dims (fixed by the reference)
static constexpr int B_ROWS = 8192;
static constexpr int F_DIM  = 1024;
static constexpr int N_DIM  = 4096;

// Fallback GEMM tiling (legacy mma.sync path, verified in R1)
static constexpr int BM = 128, BN = 128, BK = 32;
static constexpr int PAD = 8;
static constexpr int LDT = BK + PAD;

// Safety margin for the float interval bounds (slack on real data is ~2.0)
static constexpr float EPS = 0.05f;

// --------------------------- device scratch --------------------------------
__device__ __align__(16) __nv_bfloat16 g_xb[(size_t)B_ROWS * F_DIM];
__device__ __align__(16) __nv_bfloat16 g_yb[(size_t)B_ROWS * F_DIM];
__device__ __align__(16) __nv_bfloat16 g_wb[(size_t)N_DIM  * F_DIM];
__device__ float g_sumexp[B_ROWS];
__device__ float g_addvec[B_ROWS];
__device__ float g_rx[B_ROWS];          // ||x_i||
__device__ float g_ry[B_ROWS];          // ||y_i||
__device__ int   g_iYmax, g_iWmax, g_ibmax;   // float-as-int atomic maxes (>=0)
__device__ int   g_any;                 // any row needs the exact fallback?
__device__ int   g_blockfall[B_ROWS / BM];    // per-128-row-block fallback flag

// --------------------------- small kernels ---------------------------------
__global__ void k_reset() {
    int t = threadIdx.x;
    if (t == 0) { g_any = 0; g_iYmax = 0; g_iWmax = 0; g_ibmax = 0; }
    if (t < B_ROWS / BM) g_blockfall[t] = 0;
}

// One block per row: row L2 norm of a [rows, 1024] fp32 matrix.
// which: 0 = x (store g_rx), 1 = y (store g_ry + max), 2 = W (max only)
__global__ void k_rownorm(const float4* __restrict__ src, int which) {
    __shared__ float red[8];
    const int row = blockIdx.x;
    const int t   = threadIdx.x;
    float4 v = src[(size_t)row * (F_DIM / 4) + t];   // 256 threads x 4 = 1024
    float p = v.x * v.x + v.y * v.y + v.z * v.z + v.w * v.w;
    #pragma unroll
    for (int o = 16; o > 0; o >>= 1) p += __shfl_xor_sync(0xffffffffu, p, o);
    if ((t & 31) == 0) red[t >> 5] = p;
    __syncthreads();
    if (t == 0) {
        float s = 0.f;
        #pragma unroll
        for (int i = 0; i < 8; i++) s += red[i];
        float nrm = sqrtf(s);
        if (which == 0) g_rx[row] = nrm;
        else if (which == 1) { g_ry[row] = nrm; atomicMax(&g_iYmax, __float_as_int(nrm)); }
        else atomicMax(&g_iWmax, __float_as_int(nrm));
    }
}

__global__ void k_bmax(const float* __restrict__ bias) {
    __shared__ float red[8];
    const int t = threadIdx.x;
    float m = 0.f;
    for (int i = t; i < N_DIM; i += 256) m = fmaxf(m, fabsf(bias[i]));
    #pragma unroll
    for (int o = 16; o > 0; o >>= 1) m = fmaxf(m, __shfl_xor_sync(0xffffffffu, m, o));
    if ((t & 31) == 0) red[t >> 5] = m;
    __syncthreads();
    if (t == 0) {
        float s = 0.f;
        #pragma unroll
        for (int i = 0; i < 8; i++) s = fmaxf(s, red[i]);
        atomicMax(&g_ibmax, __float_as_int(s));
    }
}

// Per-row saturation proof:
//   lse_i >= log(B) - ||x_i|| * max_j ||y_j||      (Cauchy-Schwarz, all terms)
//   if that lower bound L >= 3, hardswish(lse_i) = lse_i >= L
//   min_n (y_i.W_n + b_n) >= -(||y_i|| * max_n ||W_n|| + max|b|) = -bound
//   L - bound >= 1  ==>  every output in row i clips to exactly +1.0f
__global__ void k_flags() {
    int i = blockIdx.x * blockDim.x + threadIdx.x;
    if (i >= B_ROWS) return;
    const float Ymax = __int_as_float(g_iYmax);
    const float Wmax = __int_as_float(g_iWmax);
    const float bmax = __int_as_float(g_ibmax);
    const float L = logf((float)B_ROWS) - g_rx[i] * Ymax;
    const float bound = g_ry[i] * Wmax + bmax;
    const bool sat = (L >= 3.0f + EPS) && (L - bound >= 1.0f + EPS);
    if (!sat) {
        atomicOr(&g_any, 1);
        atomicOr(&g_blockfall[i >> 7], 1);
    }
}

// Fill the whole output with 1.0f (the proven-saturated value).
__global__ void k_write_ones(float4* __restrict__ out, int n4) {
    int i = blockIdx.x * blockDim.x + threadIdx.x;
    int st = gridDim.x * blockDim.x;
    float4 one = make_float4(1.f, 1.f, 1.f, 1.f);
    for (; i < n4; i += st) out[i] = one;
}

// ----------------------- exact fallback path -------------------------------
__global__ void k_convert(const float4* __restrict__ in, int n4, int which) {
    if (g_any == 0) return;
    __nv_bfloat162* out = (which == 0) ? (__nv_bfloat162*)g_xb
                        : (which == 1) ? (__nv_bfloat162*)g_yb
                                       : (__nv_bfloat162*)g_wb;
    int i = blockIdx.x * blockDim.x + threadIdx.x;
    int st = gridDim.x * blockDim.x;
    for (; i < n4; i += st) {
        float4 v = in[i];
        out[2*i]   = __floats2bfloat162_rn(v.x, v.y);
        out[2*i+1] = __floats2bfloat162_rn(v.z, v.w);
    }
}

__global__ void k_zero_sumexp() {
    int i = blockIdx.x * blockDim.x + threadIdx.x;
    if (i < B_ROWS) g_sumexp[i] = 0.0f;
}

__global__ void k_finalize() {
    int i = blockIdx.x * blockDim.x + threadIdx.x;
    if (i < B_ROWS && g_blockfall[i >> 7]) {
        float l = logf(g_sumexp[i]);
        g_addvec[i] = l * fminf(fmaxf(l + 3.0f, 0.0f), 6.0f) * (1.0f / 6.0f);
    }
}

__device__ __forceinline__ uint32_t su32(const void* p) {
    return (uint32_t)__cvta_generic_to_shared(p);
}
__device__ __forceinline__ void cp_async16(void* smem, const void* gmem) {
    asm volatile("cp.async.cg.shared.global [%0], [%1], 16;\n"
                 :: "r"(su32(smem)), "l"(gmem));
}
__device__ __forceinline__ void ldsm_x4(uint32_t& r0, uint32_t& r1,
                                        uint32_t& r2, uint32_t& r3, uint32_t addr) {
    asm volatile("ldmatrix.sync.aligned.m8n8.x4.shared.b16 {%0,%1,%2,%3}, [%4];"
                 : "=r"(r0), "=r"(r1), "=r"(r2), "=r"(r3) : "r"(addr));
}
__device__ __forceinline__ void mma_bf16(float* c, const uint32_t* a, const uint32_t* b) {
    asm volatile(
        "mma.sync.aligned.m16n8k16.row.col.f32.bf16.bf16.f32 "
        "{%0,%1,%2,%3}, {%4,%5,%6,%7}, {%8,%9}, {%0,%1,%2,%3};"
        : "+f"(c[0]), "+f"(c[1]), "+f"(c[2]), "+f"(c[3])
        : "r"(a[0]), "r"(a[1]), "r"(a[2]), "r"(a[3]), "r"(b[0]), "r"(b[1]));
}
__device__ __forceinline__ float clamp1(float v) {
    return fminf(fmaxf(v, -1.0f), 1.0f);
}

// Warp-tiled bf16 GEMM fallback (verified in R1). Early-exits unless this
// 128-row block contains a row the bounds could not prove saturated.
// MODE 0: A=x, B=y, epilogue = sum(exp(score)) per row (atomic).
// MODE 1: A=y, B=W, epilogue = clamp(acc + bias[n] + addvec[b]).
template <int MODE>
__global__ void __launch_bounds__(256, 1)
k_gemm(const float* __restrict__ bias, float* __restrict__ out) {
    if (g_blockfall[blockIdx.x] == 0) return;

    __shared__ __nv_bfloat16 sA[2][BM * LDT];
    __shared__ __nv_bfloat16 sB[2][BN * LDT];
    __shared__ float s_sum[BM];

    const int tid    = threadIdx.x;
    const int lane   = tid & 31;
    const int warp   = tid >> 5;
    const int warp_m = warp & 1;
    const int warp_n = warp >> 1;
    const int g      = lane >> 2;
    const int t      = lane & 3;

    const int i0 = blockIdx.x * BM;
    const int j0 = blockIdx.y * BN;

    const __nv_bfloat16* Ag = ((MODE == 0) ? g_xb : g_yb) + (size_t)i0 * F_DIM;
    const __nv_bfloat16* Bg = ((MODE == 0) ? g_yb : g_wb) + (size_t)j0 * F_DIM;

    if (MODE == 0 && tid < BM) s_sum[tid] = 0.0f;

    float acc[4][4][4];
    #pragma unroll
    for (int mf = 0; mf < 4; mf++)
        #pragma unroll
        for (int nf = 0; nf < 4; nf++)
            #pragma unroll
            for (int k = 0; k < 4; k++) acc[mf][nf][k] = 0.0f;

    auto load_tile = [&](int buf, int k0) {
        #pragma unroll
        for (int p = 0; p < 2; p++) {
            int chunk = tid + p * 256;
            int row = chunk >> 2, cc = chunk & 3;
            cp_async16(&sA[buf][row * LDT + cc * 8],
                       Ag + (size_t)row * F_DIM + k0 + cc * 8);
            cp_async16(&sB[buf][row * LDT + cc * 8],
                       Bg + (size_t)row * F_DIM + k0 + cc * 8);
        }
        asm volatile("cp.async.commit_group;\n");
    };

    const int NK = F_DIM / BK;
    load_tile(0, 0);

    for (int kt = 0; kt < NK; kt++) {
        const int buf = kt & 1;
        if (kt + 1 < NK) {
            load_tile(buf ^ 1, (kt + 1) * BK);
            asm volatile("cp.async.wait_group 1;\n");
        } else {
            asm volatile("cp.async.wait_group 0;\n");
        }
        __syncthreads();

        #pragma unroll
        for (int ks = 0; ks < 2; ks++) {
            uint32_t afr[4][4];
            uint32_t bfr[4][2];
            const int q = lane >> 3, r = lane & 7;
            #pragma unroll
            for (int mf = 0; mf < 4; mf++) {
                int row = warp_m * 64 + mf * 16 + r + ((q & 1) ? 8 : 0);
                int col = ks * 16 + ((q >= 2) ? 8 : 0);
                ldsm_x4(afr[mf][0], afr[mf][1], afr[mf][2], afr[mf][3],
                        su32(&sA[buf][row * LDT + col]));
            }
            #pragma unroll
            for (int np = 0; np < 2; np++) {
                int row = warp_n * 32 + np * 16 + r + (q >> 1) * 8;
                int col = ks * 16 + (q & 1) * 8;
                ldsm_x4(bfr[2*np][0], bfr[2*np][1], bfr[2*np+1][0], bfr[2*np+1][1],
                        su32(&sB[buf][row * LDT + col]));
            }
            #pragma unroll
            for (int mf = 0; mf < 4; mf++)
                #pragma unroll
                for (int nf = 0; nf < 4; nf++)
                    mma_bf16(acc[mf][nf], afr[mf], bfr[nf]);
        }
        __syncthreads();
    }

    if (MODE == 0) {
        #pragma unroll
        for (int mf = 0; mf < 4; mf++) {
            float v0 = 0.0f, v1 = 0.0f;
            #pragma unroll
            for (int nf = 0; nf < 4; nf++) {
                v0 += __expf(acc[mf][nf][0]) + __expf(acc[mf][nf][1]);
                v1 += __expf(acc[mf][nf][2]) + __expf(acc[mf][nf][3]);
            }
            v0 += __shfl_xor_sync(0xffffffffu, v0, 1);
            v0 += __shfl_xor_sync(0xffffffffu, v0, 2);
            v1 += __shfl_xor_sync(0xffffffffu, v1, 1);
            v1 += __shfl_xor_sync(0xffffffffu, v1, 2);
            if (t == 0) {
                atomicAdd(&s_sum[warp_m * 64 + mf * 16 + g],     v0);
                atomicAdd(&s_sum[warp_m * 64 + mf * 16 + 8 + g], v1);
            }
        }
        __syncthreads();
        if (tid < BM) atomicAdd(&g_sumexp[i0 + tid], s_sum[tid]);
    } else {
        #pragma unroll
        for (int mf = 0; mf < 4; mf++) {
            int r0 = i0 + warp_m * 64 + mf * 16 + g;
            float av0 = g_addvec[r0];
            float av1 = g_addvec[r0 + 8];
            #pragma unroll
            for (int nf = 0; nf < 4; nf++) {
                int c = j0 + warp_n * 32 + nf * 8 + 2 * t;
                float b0 = bias[c], b1 = bias[c + 1];
                float2 o0, o1;
                o0.x = clamp1(acc[mf][nf][0] + b0 + av0);
                o0.y = clamp1(acc[mf][nf][1] + b1 + av0);
                o1.x = clamp1(acc[mf][nf][2] + b0 + av1);
                o1.y = clamp1(acc[mf][nf][3] + b1 + av1);
                *(float2*)&out[(size_t)r0 * N_DIM + c]       = o0;
                *(float2*)&out[(size_t)(r0 + 8) * N_DIM + c] = o1;
            }
        }
    }
}

// ---------------------------------------------------------------------------
// Launch sequence (graph-capturable: kernel launches only)
// ---------------------------------------------------------------------------
extern "C" void kernel_launch(void* const* d_in, const int* in_sizes, int n_in,
                              void* d_out, int out_size) {
    const float* x    = (const float*)d_in[0];  // [8192,1024]
    const float* y    = (const float*)d_in[1];  // [8192,1024]
    const float* w    = (const float*)d_in[2];  // [4096,1024]
    const float* bias = (const float*)d_in[3];  // [4096]
    float* out = (float*)d_out;                 // [8192,4096]

    // 1) bounds machinery
    k_reset<<<1, 256>>>();
    k_rownorm<<<B_ROWS, 256>>>((const float4*)x, 0);
    k_rownorm<<<B_ROWS, 256>>>((const float4*)y, 1);
    k_rownorm<<<N_DIM,  256>>>((const float4*)w, 2);
    k_bmax<<<1, 256>>>(bias);
    k_flags<<<B_ROWS / 256, 256>>>();

    // 2) saturated fast path: entire output is provably +1.0f
    const int n_out4 = B_ROWS * N_DIM / 4;
    k_write_ones<<<2048, 256>>>((float4*)out, n_out4);

    // 3) exact fallback for any row the bounds could not prove (early-exits
    //    per 128-row block; no-op on this data distribution)
    const int nxy4 = B_ROWS * F_DIM / 4;
    const int nw4  = N_DIM  * F_DIM / 4;
    k_convert<<<2048, 256>>>((const float4*)x, nxy4, 0);
    k_convert<<<2048, 256>>>((const float4*)y, nxy4, 1);
    k_convert<<<1024, 256>>>((const float4*)w, nw4, 2);
    k_zero_sumexp<<<(B_ROWS + 255) / 256, 256>>>();

    dim3 grid1(B_ROWS / BM, B_ROWS / BN);
    k_gemm<0><<<grid1, 256>>>(bias, out);
    k_finalize<<<(B_ROWS + 255) / 256, 256>>>();
    dim3 grid2(B_ROWS / BM, N_DIM / BN);
    k_gemm<1><<<grid2, 256>>>(bias, out);
}

// round 5
// speedup vs baseline: 16.9508x; 1.6134x over previous
#include <cuda_runtime.h>
#include <cuda_bf16.h>
#include <cstdint>
#include <math.h>

// Problem dims (fixed by the reference)
static constexpr int B_ROWS = 8192;
static constexpr int F_DIM  = 1024;
static constexpr int N_DIM  = 4096;

// Fallback GEMM tiling (legacy mma.sync path, verified in R1)
static constexpr int BM = 128, BN = 128, BK = 32;
static constexpr int PAD = 8;
static constexpr int LDT = BK + PAD;

// Safety margin for the float interval bounds (slack on real data is ~2.0)
static constexpr float EPS = 0.05f;

// --------------------------- device scratch --------------------------------
__device__ __align__(16) __nv_bfloat16 g_xb[(size_t)B_ROWS * F_DIM];
__device__ __align__(16) __nv_bfloat16 g_yb[(size_t)B_ROWS * F_DIM];
__device__ __align__(16) __nv_bfloat16 g_wb[(size_t)N_DIM  * F_DIM];
__device__ float g_sumexp[B_ROWS];
__device__ float g_addvec[B_ROWS];
__device__ float g_rx[B_ROWS];               // ||x_i||
__device__ float g_ry[B_ROWS];               // ||y_i||
__device__ float g_rw[N_DIM];                // ||W_n||
__device__ int   g_any;                      // any row needs exact fallback?
__device__ int   g_blockfall[B_ROWS / BM];   // per-128-row-block fallback flag

// ---------------------------------------------------------------------------
// K1: row L2 norms for x, y, W in ONE kernel. Warp-per-row: each lane loads
// 8 float4 (MLP=8, fully coalesced), shfl-only reduction, no atomics.
// Rows: [0,8192)=x, [8192,16384)=y, [16384,20480)=W. Grid 2560 x 256.
// ---------------------------------------------------------------------------
__global__ void __launch_bounds__(256)
k_norms(const float4* __restrict__ x, const float4* __restrict__ y,
        const float4* __restrict__ w) {
    const int gw   = (blockIdx.x * 256 + threadIdx.x) >> 5;  // global warp id
    const int lane = threadIdx.x & 31;

    const float4* src;
    float* dst;
    int row;
    if (gw < B_ROWS)            { src = x; dst = g_rx; row = gw; }
    else if (gw < 2 * B_ROWS)   { src = y; dst = g_ry; row = gw - B_ROWS; }
    else                        { src = w; dst = g_rw; row = gw - 2 * B_ROWS; }

    const float4* p = src + (size_t)row * (F_DIM / 4);
    float s = 0.0f;
    #pragma unroll
    for (int j = 0; j < 8; j++) {
        float4 v = p[lane + 32 * j];
        s += v.x * v.x + v.y * v.y + v.z * v.z + v.w * v.w;
    }
    #pragma unroll
    for (int o = 16; o > 0; o >>= 1) s += __shfl_xor_sync(0xffffffffu, s, o);
    if (lane == 0) dst[row] = sqrtf(s);
}

// ---------------------------------------------------------------------------
// K2: single-block control kernel. Computes max||y||, max||W||, max|bias|,
// runs the per-row saturation proof, writes g_blockfall/g_any, zeroes
// g_sumexp. All inputs are small and L2-hot.
//
// Proof per row i:
//   lse_i >= log(B) - ||x_i||*max_j||y_j||   (Cauchy-Schwarz on every term)
//   L >= 3      ==> hardswish(lse_i) = lse_i >= L
//   min_n(y_i.W_n + b_n) >= -(||y_i||*max_n||W_n|| + max|b|) = -bound
//   L - bound >= 1  ==> every element of row i clips to exactly +1.0f
// ---------------------------------------------------------------------------
__global__ void __launch_bounds__(1024)
k_flags(const float* __restrict__ bias) {
    __shared__ float r1[32], r2[32], r3[32];
    __shared__ int   sfall[B_ROWS / BM];
    __shared__ int   sany;
    __shared__ float sY, sW, sB;

    const int t = threadIdx.x;
    if (t < B_ROWS / BM) sfall[t] = 0;
    if (t == 0) sany = 0;

    float m1 = 0.f, m2 = 0.f, m3 = 0.f;
    for (int i = t; i < B_ROWS; i += 1024) m1 = fmaxf(m1, g_ry[i]);
    for (int i = t; i < N_DIM;  i += 1024) {
        m2 = fmaxf(m2, g_rw[i]);
        m3 = fmaxf(m3, fabsf(bias[i]));
    }
    #pragma unroll
    for (int o = 16; o > 0; o >>= 1) {
        m1 = fmaxf(m1, __shfl_xor_sync(0xffffffffu, m1, o));
        m2 = fmaxf(m2, __shfl_xor_sync(0xffffffffu, m2, o));
        m3 = fmaxf(m3, __shfl_xor_sync(0xffffffffu, m3, o));
    }
    if ((t & 31) == 0) { r1[t >> 5] = m1; r2[t >> 5] = m2; r3[t >> 5] = m3; }
    __syncthreads();
    if (t == 0) {
        float a = 0.f, b = 0.f, c = 0.f;
        #pragma unroll
        for (int i = 0; i < 32; i++) {
            a = fmaxf(a, r1[i]); b = fmaxf(b, r2[i]); c = fmaxf(c, r3[i]);
        }
        sY = a; sW = b; sB = c;
    }
    __syncthreads();

    const float Ymax = sY, Wmax = sW, bmax = sB;
    const float logB = logf((float)B_ROWS);
    for (int i = t; i < B_ROWS; i += 1024) {
        const float L     = logB - g_rx[i] * Ymax;
        const float bound = g_ry[i] * Wmax + bmax;
        const bool  sat   = (L >= 3.0f + EPS) && (L - bound >= 1.0f + EPS);
        if (!sat) { atomicOr(&sfall[i >> 7], 1); atomicOr(&sany, 1); }
        g_sumexp[i] = 0.0f;
    }
    __syncthreads();
    if (t < B_ROWS / BM) g_blockfall[t] = sfall[t];
    if (t == 0) g_any = sany;
}

// ---------------------------------------------------------------------------
// K3: fill output with the proven value (+1.0f). DRAM-write-bound floor.
// ---------------------------------------------------------------------------
__global__ void k_write_ones(float4* __restrict__ out, int n4) {
    int i  = blockIdx.x * blockDim.x + threadIdx.x;
    int st = gridDim.x * blockDim.x;
    float4 one = make_float4(1.f, 1.f, 1.f, 1.f);
    for (; i < n4; i += st) out[i] = one;
}

// ----------------------- exact fallback path (guarded) ---------------------
// K4: convert all three matrices to bf16 in one kernel. Element ranges:
// [0, 2M)=x, [2M, 4M)=y, [4M, 5M)=W in float4 units.
__global__ void k_convert_all(const float4* __restrict__ x,
                              const float4* __restrict__ y,
                              const float4* __restrict__ w) {
    if (g_any == 0) return;
    const int NX = B_ROWS * F_DIM / 4;           // 2M float4
    const int NW = N_DIM * F_DIM / 4;            // 1M float4
    int i  = blockIdx.x * blockDim.x + threadIdx.x;
    int st = gridDim.x * blockDim.x;
    for (; i < 2 * NX + NW; i += st) {
        const float4* src; __nv_bfloat162* dst; int k;
        if (i < NX)            { src = x; dst = (__nv_bfloat162*)g_xb; k = i; }
        else if (i < 2 * NX)   { src = y; dst = (__nv_bfloat162*)g_yb; k = i - NX; }
        else                   { src = w; dst = (__nv_bfloat162*)g_wb; k = i - 2 * NX; }
        float4 v = src[k];
        dst[2*k]   = __floats2bfloat162_rn(v.x, v.y);
        dst[2*k+1] = __floats2bfloat162_rn(v.z, v.w);
    }
}

__global__ void k_finalize() {
    if (g_any == 0) return;
    int i = blockIdx.x * blockDim.x + threadIdx.x;
    if (i < B_ROWS && g_blockfall[i >> 7]) {
        float l = logf(g_sumexp[i]);
        g_addvec[i] = l * fminf(fmaxf(l + 3.0f, 0.0f), 6.0f) * (1.0f / 6.0f);
    }
}

__device__ __forceinline__ uint32_t su32(const void* p) {
    return (uint32_t)__cvta_generic_to_shared(p);
}
__device__ __forceinline__ void cp_async16(void* smem, const void* gmem) {
    asm volatile("cp.async.cg.shared.global [%0], [%1], 16;\n"
                 :: "r"(su32(smem)), "l"(gmem));
}
__device__ __forceinline__ void ldsm_x4(uint32_t& r0, uint32_t& r1,
                                        uint32_t& r2, uint32_t& r3, uint32_t addr) {
    asm volatile("ldmatrix.sync.aligned.m8n8.x4.shared.b16 {%0,%1,%2,%3}, [%4];"
                 : "=r"(r0), "=r"(r1), "=r"(r2), "=r"(r3) : "r"(addr));
}
__device__ __forceinline__ void mma_bf16(float* c, const uint32_t* a, const uint32_t* b) {
    asm volatile(
        "mma.sync.aligned.m16n8k16.row.col.f32.bf16.bf16.f32 "
        "{%0,%1,%2,%3}, {%4,%5,%6,%7}, {%8,%9}, {%0,%1,%2,%3};"
        : "+f"(c[0]), "+f"(c[1]), "+f"(c[2]), "+f"(c[3])
        : "r"(a[0]), "r"(a[1]), "r"(a[2]), "r"(a[3]), "r"(b[0]), "r"(b[1]));
}
__device__ __forceinline__ float clamp1(float v) {
    return fminf(fmaxf(v, -1.0f), 1.0f);
}

// K5/K7: persistent warp-tiled bf16 GEMM fallback. Grid-stride over tiles so
// the early-exit (g_any==0) costs one ~1024-block wave, not a full tile sweep.
// MODE 0: A=x, B=y, 64x64 tiles, epilogue = sum(exp(score)) per row (atomic).
// MODE 1: A=y, B=W, 64x32 tiles, epilogue = clamp(acc + bias[n] + addvec[b]).
template <int MODE>
__global__ void __launch_bounds__(256, 1)
k_gemm(const float* __restrict__ bias, float* __restrict__ out) {
    if (g_any == 0) return;

    __shared__ __nv_bfloat16 sA[2][BM * LDT];
    __shared__ __nv_bfloat16 sB[2][BN * LDT];
    __shared__ float s_sum[BM];

    const int tid    = threadIdx.x;
    const int lane   = tid & 31;
    const int warp   = tid >> 5;
    const int warp_m = warp & 1;
    const int warp_n = warp >> 1;
    const int g      = lane >> 2;
    const int t      = lane & 3;

    const int NTN     = (MODE == 0) ? (B_ROWS / BN) : (N_DIM / BN);
    const int n_tiles = (B_ROWS / BM) * NTN;

    for (int tile = blockIdx.x; tile < n_tiles; tile += gridDim.x) {
        const int tm = tile / NTN;
        const int tn = tile % NTN;
        if (!g_blockfall[tm]) continue;

        const int i0 = tm * BM;
        const int j0 = tn * BN;
        const __nv_bfloat16* Ag = ((MODE == 0) ? g_xb : g_yb) + (size_t)i0 * F_DIM;
        const __nv_bfloat16* Bg = ((MODE == 0) ? g_yb : g_wb) + (size_t)j0 * F_DIM;

        __syncthreads();
        if (MODE == 0 && tid < BM) s_sum[tid] = 0.0f;

        float acc[4][4][4];
        #pragma unroll
        for (int mf = 0; mf < 4; mf++)
            #pragma unroll
            for (int nf = 0; nf < 4; nf++)
                #pragma unroll
                for (int k = 0; k < 4; k++) acc[mf][nf][k] = 0.0f;

        auto load_tile = [&](int buf, int k0) {
            #pragma unroll
            for (int p = 0; p < 2; p++) {
                int chunk = tid + p * 256;
                int row = chunk >> 2, cc = chunk & 3;
                cp_async16(&sA[buf][row * LDT + cc * 8],
                           Ag + (size_t)row * F_DIM + k0 + cc * 8);
                cp_async16(&sB[buf][row * LDT + cc * 8],
                           Bg + (size_t)row * F_DIM + k0 + cc * 8);
            }
            asm volatile("cp.async.commit_group;\n");
        };

        const int NK = F_DIM / BK;
        load_tile(0, 0);

        for (int kt = 0; kt < NK; kt++) {
            const int buf = kt & 1;
            if (kt + 1 < NK) {
                load_tile(buf ^ 1, (kt + 1) * BK);
                asm volatile("cp.async.wait_group 1;\n");
            } else {
                asm volatile("cp.async.wait_group 0;\n");
            }
            __syncthreads();

            #pragma unroll
            for (int ks = 0; ks < 2; ks++) {
                uint32_t afr[4][4];
                uint32_t bfr[4][2];
                const int q = lane >> 3, r = lane & 7;
                #pragma unroll
                for (int mf = 0; mf < 4; mf++) {
                    int row = warp_m * 64 + mf * 16 + r + ((q & 1) ? 8 : 0);
                    int col = ks * 16 + ((q >= 2) ? 8 : 0);
                    ldsm_x4(afr[mf][0], afr[mf][1], afr[mf][2], afr[mf][3],
                            su32(&sA[buf][row * LDT + col]));
                }
                #pragma unroll
                for (int np = 0; np < 2; np++) {
                    int row = warp_n * 32 + np * 16 + r + (q >> 1) * 8;
                    int col = ks * 16 + (q & 1) * 8;
                    ldsm_x4(bfr[2*np][0], bfr[2*np][1], bfr[2*np+1][0], bfr[2*np+1][1],
                            su32(&sB[buf][row * LDT + col]));
                }
                #pragma unroll
                for (int mf = 0; mf < 4; mf++)
                    #pragma unroll
                    for (int nf = 0; nf < 4; nf++)
                        mma_bf16(acc[mf][nf], afr[mf], bfr[nf]);
            }
            __syncthreads();
        }

        if (MODE == 0) {
            #pragma unroll
            for (int mf = 0; mf < 4; mf++) {
                float v0 = 0.0f, v1 = 0.0f;
                #pragma unroll
                for (int nf = 0; nf < 4; nf++) {
                    v0 += __expf(acc[mf][nf][0]) + __expf(acc[mf][nf][1]);
                    v1 += __expf(acc[mf][nf][2]) + __expf(acc[mf][nf][3]);
                }
                v0 += __shfl_xor_sync(0xffffffffu, v0, 1);
                v0 += __shfl_xor_sync(0xffffffffu, v0, 2);
                v1 += __shfl_xor_sync(0xffffffffu, v1, 1);
                v1 += __shfl_xor_sync(0xffffffffu, v1, 2);
                if (t == 0) {
                    atomicAdd(&s_sum[warp_m * 64 + mf * 16 + g],     v0);
                    atomicAdd(&s_sum[warp_m * 64 + mf * 16 + 8 + g], v1);
                }
            }
            __syncthreads();
            if (tid < BM) atomicAdd(&g_sumexp[i0 + tid], s_sum[tid]);
        } else {
            #pragma unroll
            for (int mf = 0; mf < 4; mf++) {
                int r0 = i0 + warp_m * 64 + mf * 16 + g;
                float av0 = g_addvec[r0];
                float av1 = g_addvec[r0 + 8];
                #pragma unroll
                for (int nf = 0; nf < 4; nf++) {
                    int c = j0 + warp_n * 32 + nf * 8 + 2 * t;
                    float b0 = bias[c], b1 = bias[c + 1];
                    float2 o0, o1;
                    o0.x = clamp1(acc[mf][nf][0] + b0 + av0);
                    o0.y = clamp1(acc[mf][nf][1] + b1 + av0);
                    o1.x = clamp1(acc[mf][nf][2] + b0 + av1);
                    o1.y = clamp1(acc[mf][nf][3] + b1 + av1);
                    *(float2*)&out[(size_t)r0 * N_DIM + c]       = o0;
                    *(float2*)&out[(size_t)(r0 + 8) * N_DIM + c] = o1;
                }
            }
        }
    }
}

// ---------------------------------------------------------------------------
// Launch sequence (graph-capturable: kernel launches only)
// ---------------------------------------------------------------------------
extern "C" void kernel_launch(void* const* d_in, const int* in_sizes, int n_in,
                              void* d_out, int out_size) {
    const float* x    = (const float*)d_in[0];  // [8192,1024]
    const float* y    = (const float*)d_in[1];  // [8192,1024]
    const float* w    = (const float*)d_in[2];  // [4096,1024]
    const float* bias = (const float*)d_in[3];  // [4096]
    float* out = (float*)d_out;                 // [8192,4096]

    // 1) row norms (x, y, W) in one pass
    k_norms<<<(2 * B_ROWS + N_DIM) / 8 / 32, 256>>>(
        (const float4*)x, (const float4*)y, (const float4*)w);

    // 2) maxes + per-row saturation proof + flags + sumexp zero (1 block)
    k_flags<<<1, 1024>>>(bias);

    // 3) saturated fast path: entire output is provably +1.0f
    k_write_ones<<<2048, 256>>>((float4*)out, B_ROWS * N_DIM / 4);

    // 4-7) exact fallback (guarded; ~one wave each when proof succeeds)
    k_convert_all<<<1024, 256>>>((const float4*)x, (const float4*)y,
                                 (const float4*)w);
    k_gemm<0><<<1024, 256>>>(bias, out);
    k_finalize<<<B_ROWS / 1024, 1024>>>();
    k_gemm<1><<<1024, 256>>>(bias, out);
}